// round 2
// baseline (speedup 1.0000x reference)
#include <cuda_runtime.h>
#include <cuda_bf16.h>

// -----------------------------------------------------------------------------
// FrustumSegmentationNet — collapsed exact-math, SINGLE fused launch.
//
// Math (proved in R0): FPS argmin always picks index 0 -> all groups identical
// -> dense-path batchnorms (axis 0, zero variance) reduce feats to the constant
//   feats = relu(be5) @ Wd3^T + bd3.
// Output = per-pixel 6->80 linear over (Kinv*[u,v,1]*z, rgb) + folded bias,
// zero outside the box.
//
// R1 change: fuse the bias-prep into every block (redundant, ~0.3us, Wd3 is
// L1-resident) and split the 80 output channels into 10 groups of 8 per
// pixel-quad -> 163,840 threads (640 blocks x 256) instead of 16,384.
// -----------------------------------------------------------------------------

#define HWPIX 65536
#define NCH   80
#define PIX   4
#define NGRP  10          // channel groups per pixel-quad
#define CPG   (NCH/NGRP)  // 8 channels per thread

__global__ __launch_bounds__(256)
void frustum_fused_kernel(const float* __restrict__ rgb,    // (H,W,3)
                          const float* __restrict__ depth,  // (H,W)
                          const float* __restrict__ intr,   // (3,3)
                          const int*   __restrict__ box,    // (5)
                          const float* __restrict__ be5,    // (256)
                          const float* __restrict__ Wd3,    // (128,256)
                          const float* __restrict__ bd3,    // (128)
                          const float* __restrict__ Ws,     // (80,134)
                          const float* __restrict__ bs,     // (80)
                          float* __restrict__ out)          // (80,H,W)
{
    __shared__ float sbe[256];       // relu(be5)
    __shared__ float sfc[128];       // constant feats vector
    __shared__ float sW[NCH * 6];    // first-6-column weights
    __shared__ float sB[NCH];        // folded bias
    __shared__ float sK[9];          // inverse intrinsic
    __shared__ int   sbox[4];

    const int t = threadIdx.x;

    // ---- stage constants ----
    sbe[t] = fmaxf(be5[t], 0.0f);
    for (int i = t; i < NCH * 6; i += 256)
        sW[i] = Ws[(i / 6) * 134 + (i % 6)];
    if (t == 0) {
        float a = intr[0], b = intr[1], c = intr[2];
        float d = intr[3], e = intr[4], f = intr[5];
        float g = intr[6], h = intr[7], i9 = intr[8];
        float det = a * (e * i9 - f * h) - b * (d * i9 - f * g) + c * (d * h - e * g);
        float inv = 1.0f / det;
        sK[0] = (e * i9 - f * h) * inv; sK[1] = (c * h - b * i9) * inv; sK[2] = (b * f - c * e) * inv;
        sK[3] = (f * g - d * i9) * inv; sK[4] = (a * i9 - c * g) * inv; sK[5] = (c * d - a * f) * inv;
        sK[6] = (d * h - e * g) * inv;  sK[7] = (b * g - a * h) * inv;  sK[8] = (a * e - b * d) * inv;
        sbox[0] = box[0]; sbox[1] = box[1]; sbox[2] = box[2]; sbox[3] = box[3];
    }
    __syncthreads();

    // ---- phase 1: fc[t] = bd3[t] + sum_k relu(be5[k]) * Wd3[t,k] ----
    if (t < 128) {
        const float4* wr = reinterpret_cast<const float4*>(Wd3 + t * 256);
        float a0 = 0.f, a1 = 0.f, a2 = 0.f, a3 = 0.f;
        #pragma unroll
        for (int k = 0; k < 64; k++) {
            float4 w = wr[k];
            a0 = fmaf(sbe[4 * k + 0], w.x, a0);
            a1 = fmaf(sbe[4 * k + 1], w.y, a1);
            a2 = fmaf(sbe[4 * k + 2], w.z, a2);
            a3 = fmaf(sbe[4 * k + 3], w.w, a3);
        }
        sfc[t] = bd3[t] + ((a0 + a1) + (a2 + a3));
    }
    __syncthreads();

    // ---- phase 2: sB[c] = bs[c] + sum_j fc[j] * Ws[c, 6+j] ----
    if (t < NCH) {
        const float* wsr = Ws + t * 134 + 6;
        float a0 = bs[t], a1 = 0.f, a2 = 0.f, a3 = 0.f;
        #pragma unroll
        for (int j = 0; j < 128; j += 4) {
            a0 = fmaf(sfc[j + 0], wsr[j + 0], a0);
            a1 = fmaf(sfc[j + 1], wsr[j + 1], a1);
            a2 = fmaf(sfc[j + 2], wsr[j + 2], a2);
            a3 = fmaf(sfc[j + 3], wsr[j + 3], a3);
        }
        sB[t] = ((a0 + a1) + (a2 + a3));
    }
    __syncthreads();

    // ---- pixel phase: (group g, quad q) per thread ----
    const int idx = blockIdx.x * 256 + t;   // 0 .. 163839
    const int g   = idx >> 14;              // 0..9 channel group
    const int q   = idx & 16383;            // pixel quad
    const int p0  = q * PIX;

    const int x1 = sbox[0], y1 = sbox[1], x2 = sbox[2], y2 = sbox[3];

    float4 dz = *reinterpret_cast<const float4*>(depth + p0);
    float zv[4] = {dz.x, dz.y, dz.z, dz.w};
    const float4* rp = reinterpret_cast<const float4*>(rgb + (size_t)p0 * 3);
    float4 r0 = rp[0], r1 = rp[1], r2 = rp[2];
    float rg[12] = {r0.x, r0.y, r0.z, r0.w, r1.x, r1.y, r1.z, r1.w,
                    r2.x, r2.y, r2.z, r2.w};

    float pc[PIX][6];
    bool  ins[PIX];
    #pragma unroll
    for (int i = 0; i < PIX; i++) {
        int p  = p0 + i;
        int r  = p >> 8;      // row
        int cc = p & 255;     // col
        ins[i] = (r >= x1) && (r < x2) && (cc >= y1) && (cc < y2);
        float u = (float)(cc - y1) + 0.5f;
        float v = (float)(r - x1) + 0.5f;
        float z = zv[i];
        pc[i][0] = (sK[0] * u + sK[1] * v + sK[2]) * z;
        pc[i][1] = (sK[3] * u + sK[4] * v + sK[5]) * z;
        pc[i][2] = (sK[6] * u + sK[7] * v + sK[8]) * z;
        pc[i][3] = rg[i * 3 + 0];
        pc[i][4] = rg[i * 3 + 1];
        pc[i][5] = rg[i * 3 + 2];
    }

    const int c0 = g * CPG;
    #pragma unroll
    for (int cc = 0; cc < CPG; cc++) {
        int c = c0 + cc;
        float w0 = sW[c * 6 + 0], w1 = sW[c * 6 + 1], w2 = sW[c * 6 + 2];
        float w3 = sW[c * 6 + 3], w4 = sW[c * 6 + 4], w5 = sW[c * 6 + 5];
        float bb = sB[c];
        float vals[PIX];
        #pragma unroll
        for (int i = 0; i < PIX; i++) {
            float s = bb;
            s = fmaf(w0, pc[i][0], s);
            s = fmaf(w1, pc[i][1], s);
            s = fmaf(w2, pc[i][2], s);
            s = fmaf(w3, pc[i][3], s);
            s = fmaf(w4, pc[i][4], s);
            s = fmaf(w5, pc[i][5], s);
            vals[i] = ins[i] ? s : 0.0f;
        }
        float4 o = {vals[0], vals[1], vals[2], vals[3]};
        *reinterpret_cast<float4*>(out + (size_t)c * HWPIX + p0) = o;
    }
}

extern "C" void kernel_launch(void* const* d_in, const int* in_sizes, int n_in,
                              void* d_out, int out_size)
{
    const float* rgb   = (const float*)d_in[0];
    const float* depth = (const float*)d_in[1];
    const float* intr  = (const float*)d_in[2];
    const int*   box   = (const int*)  d_in[3];
    const float* be5   = (const float*)d_in[23];
    const float* Wd3   = (const float*)d_in[24];
    const float* bd3   = (const float*)d_in[25];
    const float* Ws    = (const float*)d_in[26];
    const float* bs    = (const float*)d_in[27];
    float* out = (float*)d_out;

    // 16384 quads * 10 channel-groups = 163840 threads = 640 blocks * 256
    frustum_fused_kernel<<<640, 256>>>(rgb, depth, intr, box,
                                       be5, Wd3, bd3, Ws, bs, out);
}

// round 3
// speedup vs baseline: 2.6667x; 2.6667x over previous
#include <cuda_runtime.h>
#include <cuda_bf16.h>

// -----------------------------------------------------------------------------
// FrustumSegmentationNet — collapsed exact-math, two lean kernels.
//
// Math (proved in R0): FPS argmin always picks index 0 -> all 500 groups are
// identical -> the axis-0 batchnorms in the dense path see zero variance and
// collapse feats to the constant vector  feats = relu(be5) @ Wd3^T + bd3.
// Output = per-pixel 6->80 linear over (Kinv*[u,v,1]*z, rgb) + folded bias,
// zero outside the box.
//
// R3: prep kernel made coalesced + warp-parallel (reads Wd3 once, shfl
// reductions); seg kernel keeps the R2 channel-split grid (640x256) but with
// zero per-block prep.
// -----------------------------------------------------------------------------

#define HWPIX 65536
#define NCH   80
#define PIX   4

__device__ float g_adjB[NCH];

// ---- prep: g_adjB[c] = bs[c] + sum_j (bd3[j] + sum_k relu(be5[k])*Wd3[j,k]) * Ws[c,6+j]
__global__ __launch_bounds__(1024)
void frustum_prep_kernel(const float* __restrict__ be5,   // (256)
                         const float* __restrict__ Wd3,   // (128,256)
                         const float* __restrict__ bd3,   // (128)
                         const float* __restrict__ Ws,    // (80,134)
                         const float* __restrict__ bs)    // (80)
{
    __shared__ float sbe[256];
    __shared__ float sfc[128];

    const int t    = threadIdx.x;
    const int warp = t >> 5;
    const int lane = t & 31;

    if (t < 256) sbe[t] = fmaxf(be5[t], 0.0f);
    __syncthreads();

    // Phase 1: fc[j], one warp per row, coalesced float4 reads of Wd3 row j.
    for (int j = warp; j < 128; j += 32) {
        const float4* row = reinterpret_cast<const float4*>(Wd3 + j * 256);
        float4 a = row[lane];        // cols 4*lane .. 4*lane+3
        float4 b = row[lane + 32];   // cols 128+4*lane ..
        int k0 = 4 * lane, k1 = 128 + 4 * lane;
        float s = a.x * sbe[k0]     + a.y * sbe[k0 + 1]
                + a.z * sbe[k0 + 2] + a.w * sbe[k0 + 3]
                + b.x * sbe[k1]     + b.y * sbe[k1 + 1]
                + b.z * sbe[k1 + 2] + b.w * sbe[k1 + 3];
        #pragma unroll
        for (int off = 16; off > 0; off >>= 1)
            s += __shfl_down_sync(0xFFFFFFFFu, s, off);
        if (lane == 0) sfc[j] = bd3[j] + s;
    }
    __syncthreads();

    // Phase 2: adjB[c], one warp per output channel.
    for (int c = warp; c < NCH; c += 32) {
        const float* wsr = Ws + c * 134 + 6;
        float s = 0.0f;
        #pragma unroll
        for (int j = lane; j < 128; j += 32)
            s += sfc[j] * wsr[j];
        #pragma unroll
        for (int off = 16; off > 0; off >>= 1)
            s += __shfl_down_sync(0xFFFFFFFFu, s, off);
        if (lane == 0) g_adjB[c] = bs[c] + s;
    }
}

// ---- seg: thread = (channel-group of 8, pixel quad). 640 blocks x 256. ----
__global__ __launch_bounds__(256)
void frustum_seg_kernel(const float* __restrict__ rgb,    // (H,W,3)
                        const float* __restrict__ depth,  // (H,W)
                        const float* __restrict__ intr,   // (3,3)
                        const int*   __restrict__ box,    // (5)
                        const float* __restrict__ Ws,     // (80,134)
                        float* __restrict__ out)          // (80,H,W)
{
    __shared__ float sW[NCH * 6];
    __shared__ float sB[NCH];
    __shared__ float sK[9];
    __shared__ int   sbox[4];

    const int t = threadIdx.x;
    for (int i = t; i < NCH * 6; i += 256)
        sW[i] = Ws[(i / 6) * 134 + (i % 6)];
    if (t < NCH) sB[t] = g_adjB[t];
    if (t == 0) {
        float a = intr[0], b = intr[1], c = intr[2];
        float d = intr[3], e = intr[4], f = intr[5];
        float g = intr[6], h = intr[7], i9 = intr[8];
        float det = a * (e * i9 - f * h) - b * (d * i9 - f * g) + c * (d * h - e * g);
        float inv = 1.0f / det;
        sK[0] = (e * i9 - f * h) * inv; sK[1] = (c * h - b * i9) * inv; sK[2] = (b * f - c * e) * inv;
        sK[3] = (f * g - d * i9) * inv; sK[4] = (a * i9 - c * g) * inv; sK[5] = (c * d - a * f) * inv;
        sK[6] = (d * h - e * g) * inv;  sK[7] = (b * g - a * h) * inv;  sK[8] = (a * e - b * d) * inv;
        sbox[0] = box[0]; sbox[1] = box[1]; sbox[2] = box[2]; sbox[3] = box[3];
    }
    __syncthreads();

    const int idx = blockIdx.x * 256 + t;   // 0 .. 163839
    const int g   = idx >> 14;              // channel group 0..9
    const int q   = idx & 16383;            // pixel quad
    const int p0  = q * PIX;

    const int x1 = sbox[0], y1 = sbox[1], x2 = sbox[2], y2 = sbox[3];

    float4 dz = *reinterpret_cast<const float4*>(depth + p0);
    float zv[4] = {dz.x, dz.y, dz.z, dz.w};
    const float4* rp = reinterpret_cast<const float4*>(rgb + (size_t)p0 * 3);
    float4 r0 = rp[0], r1 = rp[1], r2 = rp[2];
    float rg[12] = {r0.x, r0.y, r0.z, r0.w, r1.x, r1.y, r1.z, r1.w,
                    r2.x, r2.y, r2.z, r2.w};

    float pc[PIX][6];
    bool  ins[PIX];
    #pragma unroll
    for (int i = 0; i < PIX; i++) {
        int p  = p0 + i;
        int r  = p >> 8;
        int cc = p & 255;
        ins[i] = (r >= x1) && (r < x2) && (cc >= y1) && (cc < y2);
        float u = (float)(cc - y1) + 0.5f;
        float v = (float)(r - x1) + 0.5f;
        float z = zv[i];
        pc[i][0] = (sK[0] * u + sK[1] * v + sK[2]) * z;
        pc[i][1] = (sK[3] * u + sK[4] * v + sK[5]) * z;
        pc[i][2] = (sK[6] * u + sK[7] * v + sK[8]) * z;
        pc[i][3] = rg[i * 3 + 0];
        pc[i][4] = rg[i * 3 + 1];
        pc[i][5] = rg[i * 3 + 2];
    }

    const int c0 = g * 8;
    #pragma unroll
    for (int cc = 0; cc < 8; cc++) {
        int c = c0 + cc;
        float w0 = sW[c * 6 + 0], w1 = sW[c * 6 + 1], w2 = sW[c * 6 + 2];
        float w3 = sW[c * 6 + 3], w4 = sW[c * 6 + 4], w5 = sW[c * 6 + 5];
        float bb = sB[c];
        float vals[PIX];
        #pragma unroll
        for (int i = 0; i < PIX; i++) {
            float s = bb;
            s = fmaf(w0, pc[i][0], s);
            s = fmaf(w1, pc[i][1], s);
            s = fmaf(w2, pc[i][2], s);
            s = fmaf(w3, pc[i][3], s);
            s = fmaf(w4, pc[i][4], s);
            s = fmaf(w5, pc[i][5], s);
            vals[i] = ins[i] ? s : 0.0f;
        }
        float4 o = {vals[0], vals[1], vals[2], vals[3]};
        *reinterpret_cast<float4*>(out + (size_t)c * HWPIX + p0) = o;
    }
}

extern "C" void kernel_launch(void* const* d_in, const int* in_sizes, int n_in,
                              void* d_out, int out_size)
{
    const float* rgb   = (const float*)d_in[0];
    const float* depth = (const float*)d_in[1];
    const float* intr  = (const float*)d_in[2];
    const int*   box   = (const int*)  d_in[3];
    const float* be5   = (const float*)d_in[23];
    const float* Wd3   = (const float*)d_in[24];
    const float* bd3   = (const float*)d_in[25];
    const float* Ws    = (const float*)d_in[26];
    const float* bs    = (const float*)d_in[27];
    float* out = (float*)d_out;

    frustum_prep_kernel<<<1, 1024>>>(be5, Wd3, bd3, Ws, bs);
    frustum_seg_kernel<<<640, 256>>>(rgb, depth, intr, box, Ws, out);
}